// round 1
// baseline (speedup 1.0000x reference)
#include <cuda_runtime.h>
#include <cuda_bf16.h>

#define N_NODES 50000
#define N_EDGES 600000
#define LATENT 128
#define IN_FEAT 7
#define STEPS 3

// -------- scratch (static device globals; no allocation) --------
__device__ float g_h [N_NODES * LATENT];
__device__ float g_x1[N_NODES * LATENT];
__device__ float g_x2[N_NODES * LATENT];
__device__ float g_deg_s[N_NODES];   // sender out-degree -> inv sqrt
__device__ float g_inv_s[N_NODES];
__device__ int   g_cnt_r[N_NODES];   // receiver in-degree (int)
__device__ int   g_off  [N_NODES + 1];
__device__ int   g_cursor[N_NODES];
__device__ int   g_esrc [N_EDGES];   // CSR-by-receiver: sender id per slot
__device__ int   g_incl [50176];     // 49 * 1024
__device__ int   g_bsum [64];
__device__ int   g_boff [64];

__device__ __forceinline__ float* selbuf(int s) {
    return (s == 0) ? g_h : (s == 1) ? g_x1 : g_x2;
}

// ---------------- degree / CSR build ----------------
__global__ void k_zero() {
    int i = blockIdx.x * blockDim.x + threadIdx.x;
    if (i < N_NODES) { g_deg_s[i] = 0.f; g_cnt_r[i] = 0; }
}

__global__ void k_count(const int* __restrict__ snd, const int* __restrict__ rcv) {
    int e = blockIdx.x * blockDim.x + threadIdx.x;
    if (e < N_EDGES) {
        atomicAdd(&g_deg_s[snd[e]], 1.0f);
        atomicAdd(&g_cnt_r[rcv[e]], 1);
    }
}

__global__ void k_inv_s() {
    int i = blockIdx.x * blockDim.x + threadIdx.x;
    if (i < N_NODES) g_inv_s[i] = rsqrtf(fmaxf(g_deg_s[i], 1.0f));
}

__global__ void k_scan1() {
    int i = blockIdx.x * 1024 + threadIdx.x;
    int v = (i < N_NODES) ? g_cnt_r[i] : 0;
    int x = v;
    #pragma unroll
    for (int d = 1; d < 32; d <<= 1) {
        int y = __shfl_up_sync(0xFFFFFFFFu, x, d);
        if ((threadIdx.x & 31) >= d) x += y;
    }
    __shared__ int wsum[32];
    if ((threadIdx.x & 31) == 31) wsum[threadIdx.x >> 5] = x;
    __syncthreads();
    if (threadIdx.x < 32) {
        int y = wsum[threadIdx.x];
        #pragma unroll
        for (int d = 1; d < 32; d <<= 1) {
            int z = __shfl_up_sync(0xFFFFFFFFu, y, d);
            if (threadIdx.x >= d) y += z;
        }
        wsum[threadIdx.x] = y;
    }
    __syncthreads();
    if (threadIdx.x >= 32) x += wsum[(threadIdx.x >> 5) - 1];
    g_incl[i] = x;
    if (threadIdx.x == 1023) g_bsum[blockIdx.x] = x;
}

__global__ void k_scan2(int nblocks) {
    if (threadIdx.x == 0 && blockIdx.x == 0) {
        int run = 0;
        for (int i = 0; i < nblocks; i++) { g_boff[i] = run; run += g_bsum[i]; }
    }
}

__global__ void k_scan3() {
    int i = blockIdx.x * 1024 + threadIdx.x;
    if (i < N_NODES) {
        int v = g_cnt_r[i];
        int e = g_boff[blockIdx.x] + g_incl[i] - v;  // exclusive prefix
        g_off[i] = e;
        g_cursor[i] = e;
    }
    if (i == 0) g_off[N_NODES] = N_EDGES;
}

__global__ void k_fill(const int* __restrict__ snd, const int* __restrict__ rcv) {
    int e = blockIdx.x * blockDim.x + threadIdx.x;
    if (e < N_EDGES) {
        int r = rcv[e];
        int pos = atomicAdd(&g_cursor[r], 1);
        g_esrc[pos] = snd[e];
    }
}

// ---------------- embed: h = nodes @ W_embed + b_embed ----------------
__global__ void k_embed(const float* __restrict__ nodes,
                        const float* __restrict__ Wemb,
                        const float* __restrict__ bemb) {
    int idx = blockIdx.x * blockDim.x + threadIdx.x;
    if (idx >= N_NODES * LATENT) return;
    int n = idx >> 7;
    int c = idx & 127;
    float acc = bemb[c];
    #pragma unroll
    for (int k = 0; k < IN_FEAT; k++)
        acc = fmaf(nodes[n * IN_FEAT + k], Wemb[k * LATENT + c], acc);
    g_h[idx] = acc;
}

// ---------------- GEMM: C[M,128] = act(A[M,128] @ W[128,128] + b) * rowscale ----------------
// BM=64, BN=128, BK=16, TM=8, TN=4, 256 threads
__global__ __launch_bounds__(256) void k_gemm(int srcSel, int dstSel,
                                              const float* __restrict__ W,
                                              const float* __restrict__ bias,
                                              int doRelu, int useInvS) {
    const float* __restrict__ A = selbuf(srcSel);
    float* __restrict__ C = selbuf(dstSel);

    __shared__ float Ast[16][65];   // [k][row] (transposed), padded
    __shared__ float Ws[16][128];

    int tid = threadIdx.x;
    int tx = tid & 31;   // col group: cols tx*4 .. tx*4+3
    int ty = tid >> 5;   // row group: rows ty*8 .. ty*8+7
    int rowBase = blockIdx.x * 64;

    float acc[8][4];
    #pragma unroll
    for (int i = 0; i < 8; i++)
        #pragma unroll
        for (int j = 0; j < 4; j++) acc[i][j] = 0.f;

    for (int k0 = 0; k0 < 128; k0 += 16) {
        // A tile: 64 rows x 16 k, one float4 per thread
        {
            int ar = tid >> 2;
            int kq = (tid & 3) * 4;
            int grow = rowBase + ar;
            float4 v = make_float4(0.f, 0.f, 0.f, 0.f);
            if (grow < N_NODES)
                v = *(const float4*)&A[grow * 128 + k0 + kq];
            Ast[kq + 0][ar] = v.x;
            Ast[kq + 1][ar] = v.y;
            Ast[kq + 2][ar] = v.z;
            Ast[kq + 3][ar] = v.w;
        }
        // W tile: 16 k x 128 cols, two float4 per thread
        {
            int wr = tid >> 5;
            int wc = (tid & 31) * 4;
            *(float4*)&Ws[wr][wc]     = *(const float4*)&W[(k0 + wr) * 128 + wc];
            *(float4*)&Ws[wr + 8][wc] = *(const float4*)&W[(k0 + wr + 8) * 128 + wc];
        }
        __syncthreads();

        #pragma unroll
        for (int k = 0; k < 16; k++) {
            float4 wv = *(const float4*)&Ws[k][tx * 4];
            float a[8];
            #pragma unroll
            for (int i = 0; i < 8; i++) a[i] = Ast[k][ty * 8 + i];
            #pragma unroll
            for (int i = 0; i < 8; i++) {
                acc[i][0] = fmaf(a[i], wv.x, acc[i][0]);
                acc[i][1] = fmaf(a[i], wv.y, acc[i][1]);
                acc[i][2] = fmaf(a[i], wv.z, acc[i][2]);
                acc[i][3] = fmaf(a[i], wv.w, acc[i][3]);
            }
        }
        __syncthreads();
    }

    float4 bv = *(const float4*)&bias[tx * 4];
    #pragma unroll
    for (int i = 0; i < 8; i++) {
        int row = rowBase + ty * 8 + i;
        if (row >= N_NODES) break;
        float4 o;
        o.x = acc[i][0] + bv.x;
        o.y = acc[i][1] + bv.y;
        o.z = acc[i][2] + bv.z;
        o.w = acc[i][3] + bv.w;
        if (doRelu) {
            o.x = fmaxf(o.x, 0.f); o.y = fmaxf(o.y, 0.f);
            o.z = fmaxf(o.z, 0.f); o.w = fmaxf(o.w, 0.f);
        }
        if (useInvS) {
            float rs = g_inv_s[row];
            o.x *= rs; o.y *= rs; o.z *= rs; o.w *= rs;
        }
        *(float4*)&C[row * 128 + tx * 4] = o;
    }
}

// ---------------- fused aggregate (gather by receiver) + skip + LayerNorm ----------------
// one warp per node; lane handles 4 features (float4)
__global__ __launch_bounds__(256) void k_agg_ln(const float* __restrict__ ln_scale,
                                                const float* __restrict__ ln_bias) {
    int node = blockIdx.x * 8 + (threadIdx.x >> 5);
    if (node >= N_NODES) return;
    int lane = threadIdx.x & 31;

    float4 acc = make_float4(0.f, 0.f, 0.f, 0.f);
    int b0 = g_off[node], b1 = g_off[node + 1];
    for (int j = b0; j < b1; j++) {
        int s = g_esrc[j];
        float4 v = *(const float4*)&g_x2[s * 128 + lane * 4];
        acc.x += v.x; acc.y += v.y; acc.z += v.z; acc.w += v.w;
    }
    float invr = rsqrtf(fmaxf((float)g_cnt_r[node], 1.0f));
    float4 hv = *(const float4*)&g_h[node * 128 + lane * 4];
    float4 u;
    u.x = fmaf(acc.x, invr, hv.x);
    u.y = fmaf(acc.y, invr, hv.y);
    u.z = fmaf(acc.z, invr, hv.z);
    u.w = fmaf(acc.w, invr, hv.w);

    float sum = u.x + u.y + u.z + u.w;
    float sq  = u.x * u.x + u.y * u.y + u.z * u.z + u.w * u.w;
    #pragma unroll
    for (int d = 16; d > 0; d >>= 1) {
        sum += __shfl_xor_sync(0xFFFFFFFFu, sum, d);
        sq  += __shfl_xor_sync(0xFFFFFFFFu, sq, d);
    }
    float mean = sum * (1.0f / 128.0f);
    float var = sq * (1.0f / 128.0f) - mean * mean;
    float rstd = rsqrtf(var + 1e-6f);

    float4 sc = *(const float4*)&ln_scale[lane * 4];
    float4 bi = *(const float4*)&ln_bias[lane * 4];
    float4 o;
    o.x = (u.x - mean) * rstd * sc.x + bi.x;
    o.y = (u.y - mean) * rstd * sc.y + bi.y;
    o.z = (u.z - mean) * rstd * sc.z + bi.z;
    o.w = (u.w - mean) * rstd * sc.w + bi.w;
    *(float4*)&g_h[node * 128 + lane * 4] = o;
}

// ---------------- decoder: out = h @ W_dec + b_dec ----------------
__global__ void k_decode(const float* __restrict__ Wdec,
                         const float* __restrict__ bdec,
                         float* __restrict__ out) {
    int idx = blockIdx.x * blockDim.x + threadIdx.x;
    if (idx >= N_NODES * IN_FEAT) return;
    int n = idx / IN_FEAT;
    int j = idx - n * IN_FEAT;
    float acc = bdec[j];
    const float* hrow = &g_h[n * 128];
    #pragma unroll 8
    for (int k = 0; k < 128; k++)
        acc = fmaf(hrow[k], Wdec[k * IN_FEAT + j], acc);
    out[idx] = acc;
}

extern "C" void kernel_launch(void* const* d_in, const int* in_sizes, int n_in,
                              void* d_out, int out_size) {
    const float* nodes    = (const float*)d_in[0];
    const int*   senders  = (const int*)  d_in[1];
    const int*   receivers= (const int*)  d_in[2];
    const float* W_embed  = (const float*)d_in[3];
    const float* b_embed  = (const float*)d_in[4];
    const float* mlp_W    = (const float*)d_in[5];
    const float* mlp_b    = (const float*)d_in[6];
    const float* ln_scale = (const float*)d_in[7];
    const float* ln_bias  = (const float*)d_in[8];
    const float* W_dec    = (const float*)d_in[9];
    const float* b_dec    = (const float*)d_in[10];
    float* out = (float*)d_out;

    const int SCAN_BLOCKS = (N_NODES + 1023) / 1024;  // 49

    // CSR build + degrees (once per call)
    k_zero <<<(N_NODES + 255) / 256, 256>>>();
    k_count<<<(N_EDGES + 255) / 256, 256>>>(senders, receivers);
    k_inv_s<<<(N_NODES + 255) / 256, 256>>>();
    k_scan1<<<SCAN_BLOCKS, 1024>>>();
    k_scan2<<<1, 32>>>(SCAN_BLOCKS);
    k_scan3<<<SCAN_BLOCKS, 1024>>>();
    k_fill <<<(N_EDGES + 255) / 256, 256>>>(senders, receivers);

    // embed
    k_embed<<<(N_NODES * LATENT + 255) / 256, 256>>>(nodes, W_embed, b_embed);

    const int GEMM_GRID = (N_NODES + 63) / 64;
    for (int step = 0; step < STEPS; step++) {
        const float* W0 = mlp_W + (size_t)(step * 2 + 0) * LATENT * LATENT;
        const float* W1 = mlp_W + (size_t)(step * 2 + 1) * LATENT * LATENT;
        const float* b0 = mlp_b + (size_t)(step * 2 + 0) * LATENT;
        const float* b1 = mlp_b + (size_t)(step * 2 + 1) * LATENT;
        // x1 = relu(h @ W0 + b0)
        k_gemm<<<GEMM_GRID, 256>>>(0, 1, W0, b0, 1, 0);
        // x2 = relu(x1 @ W1 + b1) * inv_sqrt_s   (scaling commutes past relu)
        k_gemm<<<GEMM_GRID, 256>>>(1, 2, W1, b1, 1, 1);
        // h = LN(h + gather-sum(x2) * inv_sqrt_r)
        k_agg_ln<<<(N_NODES + 7) / 8, 256>>>(ln_scale + step * LATENT,
                                             ln_bias + step * LATENT);
    }

    k_decode<<<(N_NODES * IN_FEAT + 255) / 256, 256>>>(W_dec, b_dec, out);
}